// round 9
// baseline (speedup 1.0000x reference)
#include <cuda_runtime.h>
#include <cuda/atomic>

// Problem shape (fixed by the dataset)
#define BB 32
#define AA 32768
#define CC 21
#define TILE 256
#define NROWBLK (AA / TILE)    // 128 blocks per row
#define HB 4096                // level-0 bins: key bits 31:20
#define RB 2048                // refine bins:  key bits 19:9
#define FULLM 0xFFFFFFFFu

// ---------------- scratch (zero-initialized BSS; left zeroed after each call) --
__device__ float    g_ce[BB * AA];      // per-anchor CE (4 MB, L2-resident)
__device__ unsigned g_hist[BB * HB];    // per-row hist of key bits 31:20
__device__ int      g_numpos[BB];
__device__ double   g_locr[BB];
__device__ double   g_pcer[BB];
__device__ int      g_arr[BB];          // per-row arrival counter
__device__ double   g_fsum;
__device__ int      g_fnp;
__device__ int      g_ticket;

// ---------------- helpers ----------------
__device__ __forceinline__ unsigned tokey(float f) {
    unsigned u = __float_as_uint(f);
    return u ^ ((u & 0x80000000u) ? 0xFFFFFFFFu : 0x80000000u);  // order-preserving
}
__device__ __forceinline__ float fromkey(unsigned k) {
    unsigned u = (k & 0x80000000u) ? (k ^ 0x80000000u) : ~k;
    return __uint_as_float(u);
}
__device__ __forceinline__ int fetch_add_acqrel(int* p) {
    cuda::atomic_ref<int, cuda::thread_scope_device> a(*p);
    return a.fetch_add(1, cuda::memory_order_acq_rel);
}

// inclusive suffix scan over NW*32 block threads.
// DEADLOCK FIX (R8): every lane of warp 0 executes every shuffle; lanes >= NW
// carry identity values instead of being predicated off the __shfl_sync.
template <int NW>
__device__ __forceinline__ unsigned suffix_scan(unsigned v, int tid) {
    __shared__ unsigned s_wt[NW];
    const int lane = tid & 31, w = tid >> 5;
    #pragma unroll
    for (int off = 1; off < 32; off <<= 1) {
        unsigned o = __shfl_down_sync(FULLM, v, off);
        if (lane + off < 32) v += o;
    }
    if (lane == 0) s_wt[w] = v;
    __syncthreads();
    if (w == 0) {                            // ALL 32 lanes of warp 0
        unsigned x  = (lane < NW) ? s_wt[lane] : 0u;
        unsigned t2 = x;
        #pragma unroll
        for (int off = 1; off < 32; off <<= 1) {
            unsigned o = __shfl_down_sync(FULLM, t2, off);
            if (lane + off < 32) t2 += o;
        }
        if (lane < NW) s_wt[lane] = t2 - x;  // strict suffix of warp totals
    }
    __syncthreads();
    v += s_wt[w];
    __syncthreads();
    return v;
}

// block-wide double sum, valid in tid 0. Same all-lane shuffle discipline.
template <int NW>
__device__ __forceinline__ double dsum(double v, int tid) {
    __shared__ double s_d[NW];
    const int lane = tid & 31, w = tid >> 5;
    #pragma unroll
    for (int o = 16; o; o >>= 1) v += __shfl_down_sync(FULLM, v, o);
    if (lane == 0) s_d[w] = v;
    __syncthreads();
    double r = 0.0;
    if (w == 0) {                            // ALL 32 lanes of warp 0
        double x = (lane < NW) ? s_d[lane] : 0.0;
        #pragma unroll
        for (int o = 16; o; o >>= 1) x += __shfl_down_sync(FULLM, x, o);
        r = x;
    }
    __syncthreads();
    return r;
}

// ---------------- the single fused kernel ----------------
__global__ void __launch_bounds__(TILE) fused_kernel(
    const float* __restrict__ loc_p, const float* __restrict__ loc_t,
    const float* __restrict__ cls_p, const int* __restrict__ cls_t,
    float* __restrict__ out)
{
    // logits staging and the refine histograms never live at the same time
    __shared__ __align__(16) union {
        float logits[TILE * CC];                       // 21504 B
        struct { unsigned rc[RB]; float rs[RB]; } ref; // 16384 B
    } u;
    __shared__ int    s_cnt[8];
    __shared__ double s_loc[8], s_pce[8];
    __shared__ int    s_isl;
    __shared__ unsigned s_d0, s_kr, s_d1, s_k2;

    const int b   = blockIdx.y;
    const int a0  = blockIdx.x * TILE;
    const int tid = threadIdx.x;

    // ======================= phase 1: streaming CE (proven ~24us) =============
    {   // coalesced float4 staging of 256x21 logits
        const float4* src = (const float4*)(cls_p + (size_t)(b * AA + a0) * CC);
        float4* dst = (float4*)u.logits;
        const int n4 = TILE * CC / 4;
        #pragma unroll
        for (int i = tid; i < n4; i += TILE) dst[i] = src[i];
    }
    __syncthreads();

    const int a  = a0 + tid;
    const int ct = cls_t[b * AA + a];
    const float* row = u.logits + tid * CC;  // stride 21 -> conflict-free

    float mx = row[0];
    #pragma unroll
    for (int c = 1; c < CC; ++c) mx = fmaxf(mx, row[c]);
    float s = 0.f;
    #pragma unroll
    for (int c = 0; c < CC; ++c) s += __expf(row[c] - mx);
    const int tgt = (ct < 0) ? 0 : ct;
    const float ce = mx + __logf(s) - row[tgt];
    g_ce[b * AA + a] = ce;

    {   // warp-aggregated count histogram (key bits 31:20)
        const unsigned dg    = tokey(ce) >> 20;
        const unsigned peers = __match_any_sync(FULLM, dg);
        if ((tid & 31) == (unsigned)(__ffs(peers) - 1))
            atomicAdd(&g_hist[b * HB + dg], (unsigned)__popc(peers));
    }

    const bool pos = (ct > 0);
    float locs = 0.f;
    if (pos) {
        float4 p = ((const float4*)loc_p)[b * AA + a];
        float4 t = ((const float4*)loc_t)[b * AA + a];
        float d;
        d = fabsf(p.x - t.x); locs += (d < 1.f) ? 0.5f * d * d : d - 0.5f;
        d = fabsf(p.y - t.y); locs += (d < 1.f) ? 0.5f * d * d : d - 0.5f;
        d = fabsf(p.z - t.z); locs += (d < 1.f) ? 0.5f * d * d : d - 0.5f;
        d = fabsf(p.w - t.w); locs += (d < 1.f) ? 0.5f * d * d : d - 0.5f;
    }

    int    cnt = pos ? 1 : 0;
    double dl  = (double)locs;
    double dp  = pos ? (double)ce : 0.0;
    #pragma unroll
    for (int o = 16; o; o >>= 1) {
        cnt += __shfl_down_sync(FULLM, cnt, o);
        dl  += __shfl_down_sync(FULLM, dl, o);
        dp  += __shfl_down_sync(FULLM, dp, o);
    }
    const int w = tid >> 5, l = tid & 31;
    if (l == 0) { s_cnt[w] = cnt; s_loc[w] = dl; s_pce[w] = dp; }
    __syncthreads();
    if (w == 0) {                            // all 32 lanes execute the shuffles
        int    c2 = (l < 8) ? s_cnt[l] : 0;
        double l2 = (l < 8) ? s_loc[l] : 0.0;
        double p2 = (l < 8) ? s_pce[l] : 0.0;
        #pragma unroll
        for (int o = 4; o; o >>= 1) {
            c2 += __shfl_down_sync(FULLM, c2, o);
            l2 += __shfl_down_sync(FULLM, l2, o);
            p2 += __shfl_down_sync(FULLM, p2, o);
        }
        if (l == 0) {
            if (c2)        atomicAdd(&g_numpos[b], c2);
            if (l2 != 0.0) atomicAdd(&g_locr[b], l2);
            if (p2 != 0.0) atomicAdd(&g_pcer[b], p2);
        }
    }

    // ======================= arrival: release this block's work ===============
    __syncthreads();                         // all writes happen-before tid0's RMW
    if (tid == 0)
        s_isl = (fetch_add_acqrel(&g_arr[b]) == NROWBLK - 1);
    __syncthreads();                         // acquire propagates block-wide
    if (!s_isl) return;

    // ======================= phase 2: row last-arriver does selection =========
    const int np = g_numpos[b];              // complete: all 128 blocks released
    long long kk = 3LL * np; if (kk > AA) kk = AA;
    const unsigned k = (unsigned)kk;

    double rowtot = 0.0;
    if (k > 0) {
        // ---- bracket k in the 12-bit histogram (16 bins/thread) ----
        unsigned c[16]; unsigned tot = 0;
        {
            const uint4* hp = (const uint4*)(g_hist + b * HB + tid * 16);
            #pragma unroll
            for (int q = 0; q < 4; ++q) {
                const uint4 v = __ldcg(hp + q);
                c[q*4+0] = v.x; c[q*4+1] = v.y; c[q*4+2] = v.z; c[q*4+3] = v.w;
                tot += v.x + v.y + v.z + v.w;
            }
        }
        {
            const unsigned A = suffix_scan<8>(tot, tid);
            unsigned ab = A - tot;           // strictly above my 16 bins
            #pragma unroll
            for (int j = 15; j >= 0; --j) {  // high bin -> low bin
                if (ab < k && k <= ab + c[j]) { s_d0 = (unsigned)(tid*16+j); s_kr = k - ab; }
                ab += c[j];
            }
        }
        __syncthreads();
        const unsigned d0 = s_d0, krem = s_kr;

        // ---- zero refine hists (reuse logits smem) ----
        #pragma unroll
        for (int j = 0; j < RB / TILE; ++j) {
            u.ref.rc[tid + j * TILE] = 0u;
            u.ref.rs[tid + j * TILE] = 0.f;
        }
        __syncthreads();

        // ---- one row pass: exact above-sum + refine hist of the boundary bin --
        double sumA = 0.0;
        {
            const float4* row4 = (const float4*)(g_ce + (size_t)b * AA);
            #pragma unroll 4
            for (int it = 0; it < AA / 4 / TILE; ++it) {   // 32 iters
                const float4 v = __ldcg(row4 + tid + it * TILE);
                const float xs[4] = {v.x, v.y, v.z, v.w};
                #pragma unroll
                for (int e = 0; e < 4; ++e) {
                    const float x = xs[e];
                    const unsigned key = tokey(x);
                    const unsigned dg  = key >> 20;
                    if (dg > d0) sumA += (double)x;
                    else if (dg == d0) {                   // rare (~3%)
                        const unsigned r = (key >> 9) & (RB - 1u);
                        atomicAdd(&u.ref.rc[r], 1u);
                        atomicAdd(&u.ref.rs[r], x);
                    }
                }
            }
        }
        __syncthreads();

        // ---- bracket krem in the refine hist (8 bins/thread) ----
        unsigned c8[8]; unsigned t8 = 0;
        #pragma unroll
        for (int j = 0; j < 8; ++j) { c8[j] = u.ref.rc[tid * 8 + j]; t8 += c8[j]; }
        {
            const unsigned A = suffix_scan<8>(t8, tid);
            unsigned ab = A - t8;
            #pragma unroll
            for (int j = 7; j >= 0; --j) {
                if (ab < krem && krem <= ab + c8[j]) { s_d1 = (unsigned)(tid*8+j); s_k2 = krem - ab; }
                ab += c8[j];
            }
        }
        __syncthreads();
        const unsigned d1 = s_d1, k2 = s_k2;

        double la = 0.0;
        #pragma unroll
        for (int j = 0; j < 8; ++j)
            if ((unsigned)(tid * 8 + j) > d1) la += (double)u.ref.rs[tid * 8 + j];

        const double above  = dsum<8>(sumA, tid);
        const double inbin  = dsum<8>(la, tid);
        if (tid == 0) {
            // ties approximated at the 23-bit prefix base: rel err <= 2^-14
            const double tie = (double)k2 * (double)fromkey((d0 << 20) | (d1 << 9));
            rowtot = above + inbin + tie;
        }
    }

    // ---- reset this row's level-0 histogram for the next graph replay ----
    {
        uint4* hp = (uint4*)(g_hist + b * HB);
        #pragma unroll
        for (int q = 0; q < HB / 4 / TILE; ++q)          // 4 uint4 per thread
            hp[tid + q * TILE] = make_uint4(0u, 0u, 0u, 0u);
    }

    if (tid == 0) {
        rowtot += g_locr[b] + g_pcer[b];
        atomicAdd(&g_fsum, rowtot);
        atomicAdd(&g_fnp, np);
        g_locr[b] = 0.0; g_pcer[b] = 0.0; g_numpos[b] = 0; g_arr[b] = 0;
        const int tk = fetch_add_acqrel(&g_ticket);      // release row, acquire all
        if (tk == BB - 1) {                              // global last finisher
            const double fs = atomicAdd(&g_fsum, 0.0);
            const int    fn = atomicAdd(&g_fnp, 0);
            out[0] = (float)(fs / (double)fn);
            g_fsum = 0.0; g_fnp = 0; g_ticket = 0;
        }
    }
}

// ---------------- launch (ONE kernel) ----------------
extern "C" void kernel_launch(void* const* d_in, const int* in_sizes, int n_in,
                              void* d_out, int out_size)
{
    const float* loc_p = (const float*)d_in[0];
    const float* loc_t = (const float*)d_in[1];
    const float* cls_p = (const float*)d_in[2];
    const int*   cls_t = (const int*)d_in[3];

    dim3 grid(NROWBLK, BB);
    fused_kernel<<<grid, TILE>>>(loc_p, loc_t, cls_p, cls_t, (float*)d_out);
}

// round 10
// speedup vs baseline: 1.5425x; 1.5425x over previous
#include <cuda_runtime.h>
#include <cuda/atomic>

// Problem shape (fixed by the dataset)
#define BB 32
#define AA 32768
#define CC 21
#define TILE 256
#define HB 4096                // level-0 bins: key bits 31:20
#define RB 2048                // refine bins:  key bits 19:9
#define FULLM 0xFFFFFFFFu

// ---------------- scratch (zero-initialized BSS; left zeroed after each call) --
__device__ float    g_ce[BB * AA];      // per-anchor CE (4 MB, L2-resident)
__device__ unsigned g_hist[BB * HB];    // per-row hist of key bits 31:20
__device__ int      g_numpos[BB];
__device__ double   g_locr[BB];
__device__ double   g_pcer[BB];
__device__ double   g_fsum;
__device__ int      g_fnp;
__device__ int      g_ticket;

// ---------------- helpers ----------------
__device__ __forceinline__ unsigned tokey(float f) {
    unsigned u = __float_as_uint(f);
    return u ^ ((u & 0x80000000u) ? 0xFFFFFFFFu : 0x80000000u);  // order-preserving
}
__device__ __forceinline__ float fromkey(unsigned k) {
    unsigned u = (k & 0x80000000u) ? (k ^ 0x80000000u) : ~k;
    return __uint_as_float(u);
}
__device__ __forceinline__ int fetch_add_acqrel(int* p) {
    cuda::atomic_ref<int, cuda::thread_scope_device> a(*p);
    return a.fetch_add(1, cuda::memory_order_acq_rel);
}

// inclusive suffix scan over 1024 block threads (proven R5 version: all lanes shuffle)
__device__ __forceinline__ unsigned suffix_scan(unsigned v, int tid) {
    __shared__ unsigned s_wt[32];
    const int lane = tid & 31, w = tid >> 5;
    #pragma unroll
    for (int off = 1; off < 32; off <<= 1) {
        unsigned o = __shfl_down_sync(FULLM, v, off);
        if (lane + off < 32) v += o;
    }
    if (lane == 0) s_wt[w] = v;
    __syncthreads();
    if (w == 0) {
        unsigned x = s_wt[lane], t2 = x;
        #pragma unroll
        for (int off = 1; off < 32; off <<= 1) {
            unsigned o = __shfl_down_sync(FULLM, t2, off);
            if (lane + off < 32) t2 += o;
        }
        s_wt[lane] = t2 - x;             // strict suffix of warp totals
    }
    __syncthreads();
    v += s_wt[w];
    __syncthreads();
    return v;
}

// block-wide double sum over 1024 threads, valid in tid 0 (all lanes shuffle)
__device__ __forceinline__ double dsum(double v, int tid) {
    __shared__ double s_d[32];
    const int lane = tid & 31, w = tid >> 5;
    #pragma unroll
    for (int o = 16; o; o >>= 1) v += __shfl_down_sync(FULLM, v, o);
    if (lane == 0) s_d[w] = v;
    __syncthreads();
    double r = 0.0;
    if (w == 0) {
        double x = s_d[lane];
        #pragma unroll
        for (int o = 16; o; o >>= 1) x += __shfl_down_sync(FULLM, x, o);
        r = x;
    }
    __syncthreads();
    return r;
}

// ---------------- kernel 1: CE + loc loss + per-row count histogram ------------
// Byte-identical to the proven ~23.6us R5 version. No fences, no tail work.
__global__ void __launch_bounds__(TILE) ce_kernel(
    const float* __restrict__ loc_p, const float* __restrict__ loc_t,
    const float* __restrict__ cls_p, const int* __restrict__ cls_t)
{
    __shared__ float sh[TILE * CC];
    __shared__ int    s_cnt[8];
    __shared__ double s_loc[8], s_pce[8];

    const int b   = blockIdx.y;
    const int a0  = blockIdx.x * TILE;
    const int tid = threadIdx.x;

    {   // coalesced float4 staging of 256x21 logits
        const float4* src = (const float4*)(cls_p + (size_t)(b * AA + a0) * CC);
        float4* dst = (float4*)sh;
        const int n4 = TILE * CC / 4;
        #pragma unroll
        for (int i = tid; i < n4; i += TILE) dst[i] = src[i];
    }
    __syncthreads();

    const int a  = a0 + tid;
    const int ct = cls_t[b * AA + a];
    const float* row = sh + tid * CC;    // stride 21 -> conflict-free

    float mx = row[0];
    #pragma unroll
    for (int c = 1; c < CC; ++c) mx = fmaxf(mx, row[c]);
    float s = 0.f;
    #pragma unroll
    for (int c = 0; c < CC; ++c) s += __expf(row[c] - mx);
    const int tgt = (ct < 0) ? 0 : ct;
    const float ce = mx + __logf(s) - row[tgt];
    g_ce[b * AA + a] = ce;

    {   // warp-aggregated count histogram (key bits 31:20)
        const unsigned dg    = tokey(ce) >> 20;
        const unsigned peers = __match_any_sync(FULLM, dg);
        if ((tid & 31) == (unsigned)(__ffs(peers) - 1))
            atomicAdd(&g_hist[b * HB + dg], (unsigned)__popc(peers));
    }

    const bool pos = (ct > 0);
    float locs = 0.f;
    if (pos) {
        float4 p = ((const float4*)loc_p)[b * AA + a];
        float4 t = ((const float4*)loc_t)[b * AA + a];
        float d;
        d = fabsf(p.x - t.x); locs += (d < 1.f) ? 0.5f * d * d : d - 0.5f;
        d = fabsf(p.y - t.y); locs += (d < 1.f) ? 0.5f * d * d : d - 0.5f;
        d = fabsf(p.z - t.z); locs += (d < 1.f) ? 0.5f * d * d : d - 0.5f;
        d = fabsf(p.w - t.w); locs += (d < 1.f) ? 0.5f * d * d : d - 0.5f;
    }

    int    cnt = pos ? 1 : 0;
    double dl  = (double)locs;
    double dp  = pos ? (double)ce : 0.0;
    #pragma unroll
    for (int o = 16; o; o >>= 1) {
        cnt += __shfl_down_sync(FULLM, cnt, o);
        dl  += __shfl_down_sync(FULLM, dl, o);
        dp  += __shfl_down_sync(FULLM, dp, o);
    }
    const int w = tid >> 5, l = tid & 31;
    if (l == 0) { s_cnt[w] = cnt; s_loc[w] = dl; s_pce[w] = dp; }
    __syncthreads();
    if (w == 0) {
        int    c2 = (l < 8) ? s_cnt[l] : 0;
        double l2 = (l < 8) ? s_loc[l] : 0.0;
        double p2 = (l < 8) ? s_pce[l] : 0.0;
        #pragma unroll
        for (int o = 4; o; o >>= 1) {
            c2 += __shfl_down_sync(FULLM, c2, o);
            l2 += __shfl_down_sync(FULLM, l2, o);
            p2 += __shfl_down_sync(FULLM, p2, o);
        }
        if (l == 0) {
            if (c2)        atomicAdd(&g_numpos[b], c2);
            if (l2 != 0.0) atomicAdd(&g_locr[b], l2);
            if (p2 != 0.0) atomicAdd(&g_pcer[b], p2);
        }
    }
}

// ---------------- kernel 2: one block per row, ZERO fences, ONE row pass -------
__global__ void __launch_bounds__(1024) select_kernel(float* __restrict__ out)
{
    const int b = blockIdx.x, tid = threadIdx.x;

    __shared__ unsigned s_c[RB];        // refine count hist (8 KB)
    __shared__ float    s_s[RB];        // refine sum hist   (8 KB)
    __shared__ unsigned s_d0, s_kr, s_cb, s_d1, s_k2;

    const int np = g_numpos[b];         // complete: kernel boundary ordered it
    long long kk = 3LL * np; if (kk > AA) kk = AA;
    const unsigned k = (unsigned)kk;

    double rowtot = 0.0;

    if (k > 0) {
        // ---- bracket k in the 12-bit histogram (4 bins/thread) ----
        {
            const uint4 cv = *(const uint4*)(g_hist + b * HB + tid * 4);
            const unsigned c4[4] = {cv.x, cv.y, cv.z, cv.w};
            const unsigned tot = c4[0] + c4[1] + c4[2] + c4[3];
            const unsigned A = suffix_scan(tot, tid);
            unsigned ab = A - tot;               // strictly above my 4 bins
            #pragma unroll
            for (int j = 3; j >= 0; --j) {       // high bin -> low bin
                if (ab < k && k <= ab + c4[j]) {
                    s_d0 = (unsigned)(tid * 4 + j); s_kr = k - ab; s_cb = c4[j];
                }
                ab += c4[j];
            }
        }
        __syncthreads();
        const unsigned d0 = s_d0, krem = s_kr, cbin = s_cb;

        // ---- zero refine hists (2 bins/thread) ----
        s_c[tid] = 0u; s_c[tid + 1024] = 0u;
        s_s[tid] = 0.f; s_s[tid + 1024] = 0.f;
        __syncthreads();

        // ---- THE row pass: exact above-sum + refine hist of boundary bin ----
        double sumA = 0.0;
        {
            const float4* row4 = (const float4*)(g_ce + (size_t)b * AA);
            #pragma unroll
            for (int it = 0; it < AA / 4 / 1024; ++it) {   // 8 iters
                const float4 v = row4[tid + it * 1024];
                const float xs[4] = {v.x, v.y, v.z, v.w};
                #pragma unroll
                for (int e = 0; e < 4; ++e) {
                    const float x = xs[e];
                    const unsigned key = tokey(x);
                    const unsigned dg  = key >> 20;
                    if (dg > d0) sumA += (double)x;
                    else if (dg == d0) {                   // ~3-5%: spread bins
                        const unsigned r = (key >> 9) & (RB - 1u);
                        atomicAdd(&s_c[r], 1u);
                        atomicAdd(&s_s[r], x);
                    }
                }
            }
        }
        __syncthreads();

        double inbin;
        if (krem == cbin) {              // whole boundary bin included: exact
            inbin = (double)s_s[tid] + (double)s_s[tid + 1024];
        } else {
            // ---- bracket krem in the refine hist (2 bins/thread) ----
            const unsigned c2[2] = {s_c[tid * 2], s_c[tid * 2 + 1]};
            const unsigned tot = c2[0] + c2[1];
            const unsigned A = suffix_scan(tot, tid);
            unsigned ab = A - tot;
            #pragma unroll
            for (int j = 1; j >= 0; --j) {
                if (ab < krem && krem <= ab + c2[j]) {
                    s_d1 = (unsigned)(tid * 2 + j); s_k2 = krem - ab;
                }
                ab += c2[j];
            }
            __syncthreads();
            const unsigned d1 = s_d1, k2 = s_k2;
            double la = 0.0;
            if ((unsigned)(tid * 2)     > d1) la += (double)s_s[tid * 2];
            if ((unsigned)(tid * 2 + 1) > d1) la += (double)s_s[tid * 2 + 1];
            inbin = la;
            if (tid == 0)                // ties at 23-bit prefix base (err<=2^-14)
                inbin += (double)k2 * (double)fromkey((d0 << 20) | (d1 << 9));
        }
        const double above = dsum(sumA, tid);
        const double inb   = dsum(inbin, tid);
        if (tid == 0) rowtot = above + inb;
    }

    // ---- reset this row's histogram for the next graph replay ----
    *(uint4*)(g_hist + b * HB + tid * 4) = make_uint4(0u, 0u, 0u, 0u);

    if (tid == 0) {
        rowtot += g_locr[b] + g_pcer[b];
        atomicAdd(&g_fsum, rowtot);      // fire-and-forget REDs
        atomicAdd(&g_fnp, np);
        g_locr[b] = 0.0; g_pcer[b] = 0.0; g_numpos[b] = 0;
        const int tk = fetch_add_acqrel(&g_ticket);   // 32 total: negligible
        if (tk == BB - 1) {              // global last finisher
            const double fs = atomicAdd(&g_fsum, 0.0);
            const int    fn = atomicAdd(&g_fnp, 0);
            out[0] = (float)(fs / (double)fn);
            g_fsum = 0.0; g_fnp = 0; g_ticket = 0;
        }
    }
}

// ---------------- launch (2 kernels) ----------------
extern "C" void kernel_launch(void* const* d_in, const int* in_sizes, int n_in,
                              void* d_out, int out_size)
{
    const float* loc_p = (const float*)d_in[0];
    const float* loc_t = (const float*)d_in[1];
    const float* cls_p = (const float*)d_in[2];
    const int*   cls_t = (const int*)d_in[3];

    dim3 grid1(AA / TILE, BB);
    ce_kernel<<<grid1, TILE>>>(loc_p, loc_t, cls_p, cls_t);
    select_kernel<<<BB, 1024>>>((float*)d_out);
}